// round 13
// baseline (speedup 1.0000x reference)
#include <cuda_runtime.h>
#include <cuda_bf16.h>
#include <math.h>
#include <stdint.h>

#define BATCH 4096
#define DIM 1024
#define NC 100000
#define NS 5000
#define NS_PAD 5120
#define LSE_OFF 20.0f

// Pure bf16 GEMM: K = DIM = 1024
#define KTOT 1024
#define TM 128
#define TN 128
#define TK 64
#define NKT (KTOT / TK)          // 16
#define NTN (NS_PAD / TN)        // 40 n-tiles
#define NTM (BATCH / TM)         // 32 m-tiles
#define NSLOT (NTN * 4 + 1)      // one slot per (n-tile, n-warp) + true slot
#define NSTAGE 3

// Megakernel block ranges (bid order = dependency order)
#define MK_CONV 1024                         // [0, 1024): convert x, 4 rows/blk
#define MK_GATHER 5120                       // [1024, 6144): gather, tile-major
#define MK_TRUE 512                          // [6144, 6656): true logits, 8 rows/blk
#define MK_GEMM (NTN * NTM)                  // [6656, 7936): GEMM, bn-major
#define MK_GATHER0 MK_CONV
#define MK_TRUE0 (MK_CONV + MK_GATHER)
#define MK_GEMM0 (MK_TRUE0 + MK_TRUE)
#define MK_GRID (MK_GEMM0 + MK_GEMM)

// ---------------------------------------------------------------------------
// Device scratch
// ---------------------------------------------------------------------------
__device__ __nv_bfloat16 g_a[(size_t)BATCH * KTOT];    // bf16(x)
__device__ __nv_bfloat16 g_b[(size_t)NS_PAD * KTOT];   // bf16(w[:, sampled])
__device__ float g_soff[NS_PAD];                       // expf(b - lec - LSE_OFF), 0 for pad
__device__ float g_true[BATCH];
__device__ float g_partial[BATCH * NSLOT];
__device__ float g_fin[32];
__device__ int g_cnt;
__device__ int g_conv_cnt;
__device__ int g_tile_cnt[NTN];

// ---------------------------------------------------------------------------
// PTX helpers (family-portable only)
// ---------------------------------------------------------------------------
__device__ __forceinline__ uint32_t smem_u32(const void* p) {
    uint32_t a;
    asm("{ .reg .u64 t; cvta.to.shared.u64 t, %1; cvt.u32.u64 %0, t; }" : "=r"(a) : "l"(p));
    return a;
}
#define CP_ASYNC16(dst, src) \
    asm volatile("cp.async.cg.shared.global [%0], [%1], 16;" :: "r"(dst), "l"(src))
#define CP_COMMIT() asm volatile("cp.async.commit_group;" ::: "memory")
#define CP_WAIT(n)  asm volatile("cp.async.wait_group %0;" :: "n"(n) : "memory")

#define LDSM_X4(r0, r1, r2, r3, addr) \
    asm volatile("ldmatrix.sync.aligned.m8n8.x4.shared.b16 {%0,%1,%2,%3}, [%4];" \
        : "=r"(r0), "=r"(r1), "=r"(r2), "=r"(r3) : "r"(addr))

#define MMA16816(d, a, b) \
    asm volatile("mma.sync.aligned.m16n8k16.row.col.f32.bf16.bf16.f32 " \
        "{%0,%1,%2,%3}, {%4,%5,%6,%7}, {%8,%9}, {%0,%1,%2,%3};" \
        : "+f"((d)[0]), "+f"((d)[1]), "+f"((d)[2]), "+f"((d)[3]) \
        : "r"((a)[0]), "r"((a)[1]), "r"((a)[2]), "r"((a)[3]), "r"((b)[0]), "r"((b)[1]))

__device__ __forceinline__ float log_expected_count(int c) {
    float cf = (float)c;
    float p = logf((cf + 2.0f) / (cf + 1.0f)) / logf((float)NC + 1.0f);
    return logf(-expm1f((float)NS * log1pf(-p)));
}

// ---------------------------------------------------------------------------
// Megakernel: convert + gather + true + GEMM(LSE) with per-tile spin flags
// SMEM (GEMM blocks only): 3 stages x 32KB + soff 512B
// ---------------------------------------------------------------------------
#define STAGE_BYTES 32768
#define STAGE_A 0
#define STAGE_B 16384
#define SM_SOFF (NSTAGE * STAGE_BYTES)       // 98304
#define SM_TOTAL (SM_SOFF + TN * 4)          // 98816

__global__ __launch_bounds__(256, 2)
void mega_kernel(const float* __restrict__ x,
                 const float* __restrict__ w,
                 const float* __restrict__ b,
                 const int* __restrict__ labels,
                 const int* __restrict__ sampled) {
    int blk = blockIdx.x;
    int tid = threadIdx.x;

    // ================= convert x -> bf16 (4 rows per block) =================
    if (blk < MK_CONV) {
        int r0 = blk * 4;
        #pragma unroll
        for (int rr = 0; rr < 4; rr++) {
            const float4 v = *(const float4*)(x + (size_t)(r0 + rr) * DIM + tid * 4);
            __nv_bfloat162* ar = (__nv_bfloat162*)(g_a + (size_t)(r0 + rr) * KTOT);
            ar[tid * 2]     = __floats2bfloat162_rn(v.x, v.y);
            ar[tid * 2 + 1] = __floats2bfloat162_rn(v.z, v.w);
        }
        __threadfence();
        __syncthreads();
        if (tid == 0) atomicAdd(&g_conv_cnt, 1);
        return;
    }

    // ================= gather w[:, sampled] -> bf16 (1 col per block) =======
    if (blk < MK_TRUE0) {
        int s = blk - MK_GATHER0;
        __nv_bfloat16* br = g_b + (size_t)s * KTOT;
        if (s < NS) {
            int c = sampled[s];
            const float* wc = w + c;
            float v[4];
            #pragma unroll
            for (int u = 0; u < 4; u++)
                v[u] = wc[(size_t)(tid + u * 256) * NC];
            #pragma unroll
            for (int u = 0; u < 4; u++)
                br[tid + u * 256] = __float2bfloat16(v[u]);
            if (tid == 0)
                g_soff[s] = expf(b[c] - log_expected_count(c) - LSE_OFF);
        } else {
            __nv_bfloat16 z = __float2bfloat16(0.0f);
            #pragma unroll
            for (int u = 0; u < 4; u++)
                br[tid + u * 256] = z;
            if (tid == 0)
                g_soff[s] = 0.0f;
        }
        __threadfence();
        __syncthreads();
        if (tid == 0) atomicAdd(&g_tile_cnt[s >> 7], 1);
        return;
    }

    // ================= true logits (8 rows per block) ========================
    if (blk < MK_GEMM0) {
        int r = (blk - MK_TRUE0) * 8 + (tid >> 5);
        int lane = tid & 31;
        int c = labels[r];
        const float* xr = x + (size_t)r * DIM;
        const float* wc = w + c;
        float s = 0.0f;
        #pragma unroll
        for (int u = 0; u < 8; u++) {
            float s2 = 0.0f;
            #pragma unroll
            for (int q = 0; q < 4; q++) {
                int d = lane + (u * 4 + q) * 32;
                s2 += xr[d] * wc[(size_t)d * NC];
            }
            s += s2;
        }
        #pragma unroll
        for (int o = 16; o; o >>= 1)
            s += __shfl_xor_sync(0xffffffffu, s, o);
        if (lane == 0) {
            float t = s + b[c] - log_expected_count(c);
            g_true[r] = t;
            g_partial[r * NSLOT + NSLOT - 1] = expf(t - LSE_OFF);
        }
        return;
    }

    // ================= GEMM + fused LSE epilogue (bn-major) =================
    extern __shared__ char smem[];
    const uint32_t sbase = smem_u32(smem);
    float* soff_s = (float*)(smem + SM_SOFF);

    int g = blk - MK_GEMM0;
    int bn = g / NTM;
    int bm = g % NTM;
    int m0 = bm * TM;
    int n0 = bn * TN;

    // Wait for A conversion + this B tile's gather (device-scope atomics)
    if (tid == 0) {
        while (atomicAdd(&g_conv_cnt, 0) < MK_CONV) {}
        while (atomicAdd(&g_tile_cnt[bn], 0) < 128) {}
    }
    __syncthreads();

    int lane = tid & 31;
    int wid = tid >> 5;
    int wm = wid & 1;          // 2 m-warps (64 rows each)
    int wn = wid >> 1;         // 4 n-warps (32 cols each)

    const __nv_bfloat16* ga = g_a + (size_t)m0 * KTOT;
    const __nv_bfloat16* gb = g_b + (size_t)n0 * KTOT;

    if (tid < TN) soff_s[tid] = g_soff[n0 + tid];

    int lrow = tid >> 3;            // 0..31 (+32 per i)
    int lc   = tid & 7;             // 16B chunk 0..7
    uint32_t swrow = (uint32_t)(lrow * 128 + ((lc ^ (lrow & 7)) * 16));

    float acc[4][4][4];
    #pragma unroll
    for (int i = 0; i < 4; i++)
        #pragma unroll
        for (int j = 0; j < 4; j++)
            #pragma unroll
            for (int v = 0; v < 4; v++) acc[i][j][v] = 0.0f;

    // Prologue: prefetch stages 0 and 1
    #pragma unroll
    for (int pf = 0; pf < 2; pf++) {
        uint32_t sb = sbase + pf * STAGE_BYTES;
        int kk = pf * TK;
        #pragma unroll
        for (int i = 0; i < 4; i++) {
            int row = lrow + i * 32;
            CP_ASYNC16(sb + STAGE_A + swrow + (uint32_t)(i * 32 * 128),
                       ga + (size_t)row * KTOT + kk + lc * 8);
            CP_ASYNC16(sb + STAGE_B + swrow + (uint32_t)(i * 32 * 128),
                       gb + (size_t)row * KTOT + kk + lc * 8);
        }
        CP_COMMIT();
    }

    // LDSM base offsets; across ks-steps the swizzled address is off ^ (ks*32)
    int mat = lane >> 3;
    int lr8 = lane & 7;
    int msel = (mat & 1) << 3;
    int csel = mat >> 1;

    uint32_t offA[4], offB[2];
    #pragma unroll
    for (int i = 0; i < 4; i++) {
        int r = wm * 64 + i * 16 + lr8 + msel;
        offA[i] = (uint32_t)(r * 128 + ((csel ^ (r & 7)) * 16));
    }
    #pragma unroll
    for (int p = 0; p < 2; p++) {
        int r = wn * 32 + p * 16 + lr8 + msel;
        offB[p] = (uint32_t)(r * 128 + ((csel ^ (r & 7)) * 16));
    }

    int sidx = 0;
    for (int it = 0; it < NKT; it++) {
        if (it < NKT - 1) { CP_WAIT(1); } else { CP_WAIT(0); }
        __syncthreads();

        if (it + 2 < NKT) {
            int pidx = sidx + 2; if (pidx >= NSTAGE) pidx -= NSTAGE;
            uint32_t sb = sbase + pidx * STAGE_BYTES;
            int kk = (it + 2) * TK;
            #pragma unroll
            for (int i = 0; i < 4; i++) {
                int row = lrow + i * 32;
                CP_ASYNC16(sb + STAGE_A + swrow + (uint32_t)(i * 32 * 128),
                           ga + (size_t)row * KTOT + kk + lc * 8);
                CP_ASYNC16(sb + STAGE_B + swrow + (uint32_t)(i * 32 * 128),
                           gb + (size_t)row * KTOT + kk + lc * 8);
            }
            CP_COMMIT();
        }

        uint32_t abase = sbase + sidx * STAGE_BYTES + STAGE_A;
        uint32_t bbase = sbase + sidx * STAGE_BYTES + STAGE_B;

        #pragma unroll
        for (int ks = 0; ks < 4; ks++) {
            uint32_t kx = (uint32_t)(ks * 32);
            uint32_t a[4][4], bfr[4][2];
            #pragma unroll
            for (int i = 0; i < 4; i++)
                LDSM_X4(a[i][0], a[i][1], a[i][2], a[i][3], abase + (offA[i] ^ kx));
            #pragma unroll
            for (int p = 0; p < 2; p++) {
                uint32_t t0, t1, t2, t3;
                LDSM_X4(t0, t1, t2, t3, bbase + (offB[p] ^ kx));
                bfr[2 * p][0] = t0;     bfr[2 * p][1] = t2;
                bfr[2 * p + 1][0] = t1; bfr[2 * p + 1][1] = t3;
            }
            #pragma unroll
            for (int i = 0; i < 4; i++)
                #pragma unroll
                for (int j = 0; j < 4; j++)
                    MMA16816(acc[i][j], a[i], bfr[j]);
        }
        sidx++; if (sidx >= NSTAGE) sidx = 0;
    }

    // Fused epilogue: sum += __expf(acc) * exp_factor (pad cols have factor 0)
    float sr0[4], sr1[4];
    #pragma unroll
    for (int i = 0; i < 4; i++) { sr0[i] = 0.0f; sr1[i] = 0.0f; }

    #pragma unroll
    for (int j = 0; j < 4; j++) {
        int l = wn * 32 + j * 8 + 2 * (lane & 3);
        float e0 = soff_s[l];
        float e1 = soff_s[l + 1];
        #pragma unroll
        for (int i = 0; i < 4; i++) {
            sr0[i] = fmaf(__expf(acc[i][j][0]), e0, sr0[i]);
            sr0[i] = fmaf(__expf(acc[i][j][1]), e1, sr0[i]);
            sr1[i] = fmaf(__expf(acc[i][j][2]), e0, sr1[i]);
            sr1[i] = fmaf(__expf(acc[i][j][3]), e1, sr1[i]);
        }
    }
    #pragma unroll
    for (int i = 0; i < 4; i++) {
        sr0[i] += __shfl_xor_sync(0xffffffffu, sr0[i], 1);
        sr0[i] += __shfl_xor_sync(0xffffffffu, sr0[i], 2);
        sr1[i] += __shfl_xor_sync(0xffffffffu, sr1[i], 1);
        sr1[i] += __shfl_xor_sync(0xffffffffu, sr1[i], 2);
    }
    if ((lane & 3) == 0) {
        int slot = bn * 4 + wn;
        #pragma unroll
        for (int i = 0; i < 4; i++) {
            int r0 = m0 + wm * 64 + i * 16 + (lane >> 2);
            g_partial[r0 * NSLOT + slot] = sr0[i];
            g_partial[(r0 + 8) * NSLOT + slot] = sr1[i];
        }
    }
}

// ---------------------------------------------------------------------------
// Final reduction, single launch; last block also resets all flags for replay
// ---------------------------------------------------------------------------
__global__ void final_kernel(float* __restrict__ out) {
    __shared__ float red[128];
    __shared__ int is_last;
    int r = blockIdx.x * 128 + threadIdx.x;
    float s = 0.0f;
    #pragma unroll 8
    for (int t = 0; t < NSLOT; t++)
        s += g_partial[r * NSLOT + t];
    float acc = LSE_OFF + logf(s) - g_true[r];
    red[threadIdx.x] = acc;
    __syncthreads();
    for (int st = 64; st; st >>= 1) {
        if (threadIdx.x < st) red[threadIdx.x] += red[threadIdx.x + st];
        __syncthreads();
    }
    if (threadIdx.x == 0) {
        g_fin[blockIdx.x] = red[0];
        __threadfence();
        int old = atomicAdd(&g_cnt, 1);
        is_last = (old == 31) ? 1 : 0;
    }
    __syncthreads();
    if (is_last) {
        // reset pipeline flags for the next graph replay
        if (threadIdx.x < NTN) g_tile_cnt[threadIdx.x] = 0;
        if (threadIdx.x == 64) g_conv_cnt = 0;
        if (threadIdx.x < 32) {
            __threadfence();
            float v = g_fin[threadIdx.x];
            #pragma unroll
            for (int o = 16; o; o >>= 1)
                v += __shfl_xor_sync(0xffffffffu, v, o);
            if (threadIdx.x == 0) {
                out[0] = v / (float)BATCH;
                g_cnt = 0;
            }
        }
    }
}

// ---------------------------------------------------------------------------
extern "C" void kernel_launch(void* const* d_in, const int* in_sizes, int n_in,
                              void* d_out, int out_size) {
    const float* x       = (const float*)d_in[0];
    const float* w       = (const float*)d_in[1];
    const float* b       = (const float*)d_in[2];
    const int*   labels  = (const int*)d_in[3];
    const int*   sampled = (const int*)d_in[4];
    float* out = (float*)d_out;

    cudaFuncSetAttribute(mega_kernel,
                         cudaFuncAttributeMaxDynamicSharedMemorySize, SM_TOTAL);

    mega_kernel<<<MK_GRID, 256, SM_TOTAL>>>(x, w, b, labels, sampled);
    final_kernel<<<32, 128>>>(out);
}

// round 14
// speedup vs baseline: 1.1432x; 1.1432x over previous
#include <cuda_runtime.h>
#include <cuda_bf16.h>
#include <math.h>
#include <stdint.h>

#define BATCH 4096
#define DIM 1024
#define NC 100000
#define NS 5000
#define NS_PAD 5120
#define LSE_OFF 20.0f

// Pure bf16 GEMM: K = DIM = 1024
#define KTOT 1024
#define TM 128
#define TN 128
#define TK 64
#define NKT (KTOT / TK)          // 16
#define NTN (NS_PAD / TN)        // 40 n-tiles
#define NTM (BATCH / TM)         // 32 m-tiles
#define GEMM_BLKS (NTN * NTM)    // 1280
#define TRUE_BLKS 512            // 8 rows per block
#define NSLOT (NTN * 4 + 1)      // one slot per (n-tile, n-warp) + true slot
#define NSTAGE 3

// Prep kernel block ranges (gather + convert; true folded into GEMM tail)
#define PREP_GATHER 5120
#define PREP_CONV 1024           // 4 rows per block
#define PREP_GRID (PREP_GATHER + PREP_CONV)

#define FIN_BLKS 512             // warp-per-row final reduction

// ---------------------------------------------------------------------------
// Device scratch
// ---------------------------------------------------------------------------
__device__ __nv_bfloat16 g_a[(size_t)BATCH * KTOT];    // bf16(x)
__device__ __nv_bfloat16 g_b[(size_t)NS_PAD * KTOT];   // bf16(w[:, sampled])
__device__ float g_soff[NS_PAD];                       // expf(b - lec - LSE_OFF), 0 for pad
__device__ float g_true[BATCH];
__device__ float g_partial[BATCH * NSLOT];
__device__ float g_fin[FIN_BLKS];
__device__ int g_cnt;

// ---------------------------------------------------------------------------
// PTX helpers (family-portable only)
// ---------------------------------------------------------------------------
__device__ __forceinline__ uint32_t smem_u32(const void* p) {
    uint32_t a;
    asm("{ .reg .u64 t; cvta.to.shared.u64 t, %1; cvt.u32.u64 %0, t; }" : "=r"(a) : "l"(p));
    return a;
}
#define CP_ASYNC16(dst, src) \
    asm volatile("cp.async.cg.shared.global [%0], [%1], 16;" :: "r"(dst), "l"(src))
#define CP_COMMIT() asm volatile("cp.async.commit_group;" ::: "memory")
#define CP_WAIT(n)  asm volatile("cp.async.wait_group %0;" :: "n"(n) : "memory")

#define LDSM_X4(r0, r1, r2, r3, addr) \
    asm volatile("ldmatrix.sync.aligned.m8n8.x4.shared.b16 {%0,%1,%2,%3}, [%4];" \
        : "=r"(r0), "=r"(r1), "=r"(r2), "=r"(r3) : "r"(addr))

#define MMA16816(d, a, b) \
    asm volatile("mma.sync.aligned.m16n8k16.row.col.f32.bf16.bf16.f32 " \
        "{%0,%1,%2,%3}, {%4,%5,%6,%7}, {%8,%9}, {%0,%1,%2,%3};" \
        : "+f"((d)[0]), "+f"((d)[1]), "+f"((d)[2]), "+f"((d)[3]) \
        : "r"((a)[0]), "r"((a)[1]), "r"((a)[2]), "r"((a)[3]), "r"((b)[0]), "r"((b)[1]))

__device__ __forceinline__ float log_expected_count(int c) {
    float cf = (float)c;
    float p = logf((cf + 2.0f) / (cf + 1.0f)) / logf((float)NC + 1.0f);
    return logf(-expm1f((float)NS * log1pf(-p)));
}

// ---------------------------------------------------------------------------
// Kernel 1 (prep): gather B (bf16) + exp-factor, convert A (bf16)
// ---------------------------------------------------------------------------
__global__ void prep_kernel(const float* __restrict__ x,
                            const float* __restrict__ w,
                            const float* __restrict__ b,
                            const int* __restrict__ sampled) {
    int blk = blockIdx.x;
    int tid = threadIdx.x;

    if (blk < PREP_GATHER) {
        int s = blk;
        __nv_bfloat16* br = g_b + (size_t)s * KTOT;
        if (s < NS) {
            int c = sampled[s];
            const float* wc = w + c;
            float v[4];
            #pragma unroll
            for (int u = 0; u < 4; u++)
                v[u] = wc[(size_t)(tid + u * 256) * NC];
            #pragma unroll
            for (int u = 0; u < 4; u++)
                br[tid + u * 256] = __float2bfloat16(v[u]);
            if (tid == 0)
                g_soff[s] = expf(b[c] - log_expected_count(c) - LSE_OFF);
        } else {
            __nv_bfloat16 z = __float2bfloat16(0.0f);
            #pragma unroll
            for (int u = 0; u < 4; u++)
                br[tid + u * 256] = z;
            if (tid == 0)
                g_soff[s] = 0.0f;
        }
    } else {
        int r0 = (blk - PREP_GATHER) * 4;
        #pragma unroll
        for (int rr = 0; rr < 4; rr++) {
            const float4 v = *(const float4*)(x + (size_t)(r0 + rr) * DIM + tid * 4);
            __nv_bfloat162* ar = (__nv_bfloat162*)(g_a + (size_t)(r0 + rr) * KTOT);
            ar[tid * 2]     = __floats2bfloat162_rn(v.x, v.y);
            ar[tid * 2 + 1] = __floats2bfloat162_rn(v.z, v.w);
        }
    }
}

// ---------------------------------------------------------------------------
// Kernel 2: bf16 mma.sync GEMM 128x128xK1024 (blocks 0..1279) +
//           true-logit warp-dots (blocks 1280..1791), fused LSE epilogue
// SMEM per stage: A 16KB + B 16KB = 32KB; 3 stages = 96KB; soff 512B
// ---------------------------------------------------------------------------
#define STAGE_BYTES 32768
#define STAGE_A 0
#define STAGE_B 16384
#define SM_SOFF (NSTAGE * STAGE_BYTES)       // 98304
#define SM_TOTAL (SM_SOFF + TN * 4)          // 98816

__global__ __launch_bounds__(256, 2)
void gemm_lse_kernel(const float* __restrict__ x,
                     const float* __restrict__ w,
                     const float* __restrict__ b,
                     const int* __restrict__ labels) {
    int tid = threadIdx.x;

    // ---- true-logit blocks (fill GEMM tail waves) ----
    if (blockIdx.x >= GEMM_BLKS) {
        int r = (blockIdx.x - GEMM_BLKS) * 8 + (tid >> 5);
        int lane = tid & 31;
        int c = labels[r];
        const float* xr = x + (size_t)r * DIM;
        const float* wc = w + c;
        float s = 0.0f;
        #pragma unroll
        for (int u = 0; u < 8; u++) {
            float s2 = 0.0f;
            #pragma unroll
            for (int q = 0; q < 4; q++) {
                int d = lane + (u * 4 + q) * 32;
                s2 += xr[d] * wc[(size_t)d * NC];
            }
            s += s2;
        }
        #pragma unroll
        for (int o = 16; o; o >>= 1)
            s += __shfl_xor_sync(0xffffffffu, s, o);
        if (lane == 0) {
            float t = s + b[c] - log_expected_count(c);
            g_true[r] = t;
            g_partial[r * NSLOT + NSLOT - 1] = expf(t - LSE_OFF);
        }
        return;
    }

    // ---- GEMM blocks ----
    extern __shared__ char smem[];
    const uint32_t sbase = smem_u32(smem);
    float* soff_s = (float*)(smem + SM_SOFF);

    int lane = tid & 31;
    int wid = tid >> 5;
    int wm = wid & 1;          // 2 m-warps (64 rows each)
    int wn = wid >> 1;         // 4 n-warps (32 cols each)
    int bn = blockIdx.x % NTN;
    int bm = blockIdx.x / NTN;
    int m0 = bm * TM;
    int n0 = bn * TN;

    const __nv_bfloat16* ga = g_a + (size_t)m0 * KTOT;
    const __nv_bfloat16* gb = g_b + (size_t)n0 * KTOT;

    if (tid < TN) soff_s[tid] = g_soff[n0 + tid];

    int lrow = tid >> 3;            // 0..31 (+32 per i)
    int lc   = tid & 7;             // 16B chunk 0..7
    uint32_t swrow = (uint32_t)(lrow * 128 + ((lc ^ (lrow & 7)) * 16));

    float acc[4][4][4];
    #pragma unroll
    for (int i = 0; i < 4; i++)
        #pragma unroll
        for (int j = 0; j < 4; j++)
            #pragma unroll
            for (int v = 0; v < 4; v++) acc[i][j][v] = 0.0f;

    // Prologue: prefetch stages 0 and 1
    #pragma unroll
    for (int pf = 0; pf < 2; pf++) {
        uint32_t sb = sbase + pf * STAGE_BYTES;
        int kk = pf * TK;
        #pragma unroll
        for (int i = 0; i < 4; i++) {
            int row = lrow + i * 32;
            CP_ASYNC16(sb + STAGE_A + swrow + (uint32_t)(i * 32 * 128),
                       ga + (size_t)row * KTOT + kk + lc * 8);
            CP_ASYNC16(sb + STAGE_B + swrow + (uint32_t)(i * 32 * 128),
                       gb + (size_t)row * KTOT + kk + lc * 8);
        }
        CP_COMMIT();
    }

    // LDSM base offsets; across ks-steps the swizzled address is off ^ (ks*32)
    int mat = lane >> 3;
    int lr8 = lane & 7;
    int msel = (mat & 1) << 3;
    int csel = mat >> 1;

    uint32_t offA[4], offB[2];
    #pragma unroll
    for (int i = 0; i < 4; i++) {
        int r = wm * 64 + i * 16 + lr8 + msel;
        offA[i] = (uint32_t)(r * 128 + ((csel ^ (r & 7)) * 16));
    }
    #pragma unroll
    for (int p = 0; p < 2; p++) {
        int r = wn * 32 + p * 16 + lr8 + msel;
        offB[p] = (uint32_t)(r * 128 + ((csel ^ (r & 7)) * 16));
    }

    int sidx = 0;
    for (int it = 0; it < NKT; it++) {
        if (it < NKT - 1) { CP_WAIT(1); } else { CP_WAIT(0); }
        __syncthreads();

        if (it + 2 < NKT) {
            int pidx = sidx + 2; if (pidx >= NSTAGE) pidx -= NSTAGE;
            uint32_t sb = sbase + pidx * STAGE_BYTES;
            int kk = (it + 2) * TK;
            #pragma unroll
            for (int i = 0; i < 4; i++) {
                int row = lrow + i * 32;
                CP_ASYNC16(sb + STAGE_A + swrow + (uint32_t)(i * 32 * 128),
                           ga + (size_t)row * KTOT + kk + lc * 8);
                CP_ASYNC16(sb + STAGE_B + swrow + (uint32_t)(i * 32 * 128),
                           gb + (size_t)row * KTOT + kk + lc * 8);
            }
            CP_COMMIT();
        }

        uint32_t abase = sbase + sidx * STAGE_BYTES + STAGE_A;
        uint32_t bbase = sbase + sidx * STAGE_BYTES + STAGE_B;

        #pragma unroll
        for (int ks = 0; ks < 4; ks++) {
            uint32_t kx = (uint32_t)(ks * 32);
            uint32_t a[4][4], bfr[4][2];
            #pragma unroll
            for (int i = 0; i < 4; i++)
                LDSM_X4(a[i][0], a[i][1], a[i][2], a[i][3], abase + (offA[i] ^ kx));
            #pragma unroll
            for (int p = 0; p < 2; p++) {
                uint32_t t0, t1, t2, t3;
                LDSM_X4(t0, t1, t2, t3, bbase + (offB[p] ^ kx));
                bfr[2 * p][0] = t0;     bfr[2 * p][1] = t2;
                bfr[2 * p + 1][0] = t1; bfr[2 * p + 1][1] = t3;
            }
            #pragma unroll
            for (int i = 0; i < 4; i++)
                #pragma unroll
                for (int j = 0; j < 4; j++)
                    MMA16816(acc[i][j], a[i], bfr[j]);
        }
        sidx++; if (sidx >= NSTAGE) sidx = 0;
    }

    // Fused epilogue: sum += __expf(acc) * exp_factor (pad cols have factor 0)
    float sr0[4], sr1[4];
    #pragma unroll
    for (int i = 0; i < 4; i++) { sr0[i] = 0.0f; sr1[i] = 0.0f; }

    #pragma unroll
    for (int j = 0; j < 4; j++) {
        int l = wn * 32 + j * 8 + 2 * (lane & 3);
        float e0 = soff_s[l];
        float e1 = soff_s[l + 1];
        #pragma unroll
        for (int i = 0; i < 4; i++) {
            sr0[i] = fmaf(__expf(acc[i][j][0]), e0, sr0[i]);
            sr0[i] = fmaf(__expf(acc[i][j][1]), e1, sr0[i]);
            sr1[i] = fmaf(__expf(acc[i][j][2]), e0, sr1[i]);
            sr1[i] = fmaf(__expf(acc[i][j][3]), e1, sr1[i]);
        }
    }
    #pragma unroll
    for (int i = 0; i < 4; i++) {
        sr0[i] += __shfl_xor_sync(0xffffffffu, sr0[i], 1);
        sr0[i] += __shfl_xor_sync(0xffffffffu, sr0[i], 2);
        sr1[i] += __shfl_xor_sync(0xffffffffu, sr1[i], 1);
        sr1[i] += __shfl_xor_sync(0xffffffffu, sr1[i], 2);
    }
    if ((lane & 3) == 0) {
        int slot = bn * 4 + wn;
        #pragma unroll
        for (int i = 0; i < 4; i++) {
            int r0 = m0 + wm * 64 + i * 16 + (lane >> 2);
            g_partial[r0 * NSLOT + slot] = sr0[i];
            g_partial[(r0 + 8) * NSLOT + slot] = sr1[i];
        }
    }
}

// ---------------------------------------------------------------------------
// Kernel 3: final reduction, warp-per-row (512 blocks x 256 thr); last block
//           sums the 512 block partials. Counter self-resets for graph replay.
// ---------------------------------------------------------------------------
__global__ void final_kernel(float* __restrict__ out) {
    __shared__ float red[8];
    __shared__ int is_last;
    int wid = threadIdx.x >> 5;
    int lane = threadIdx.x & 31;
    int r = blockIdx.x * 8 + wid;

    const float* row = g_partial + (size_t)r * NSLOT;
    float s = 0.0f;
    #pragma unroll
    for (int t = lane; t < NSLOT; t += 32)
        s += row[t];
    #pragma unroll
    for (int o = 16; o; o >>= 1)
        s += __shfl_xor_sync(0xffffffffu, s, o);
    if (lane == 0)
        red[wid] = LSE_OFF + logf(s) - g_true[r];
    __syncthreads();

    if (threadIdx.x == 0) {
        float acc = 0.0f;
        #pragma unroll
        for (int i = 0; i < 8; i++) acc += red[i];
        g_fin[blockIdx.x] = acc;
        __threadfence();
        int old = atomicAdd(&g_cnt, 1);
        is_last = (old == FIN_BLKS - 1) ? 1 : 0;
    }
    __syncthreads();

    if (is_last) {
        __threadfence();
        float v = 0.0f;
        // 256 threads, 2 values each, deterministic order
        v = g_fin[threadIdx.x] + g_fin[threadIdx.x + 256];
        __shared__ float red2[256];
        red2[threadIdx.x] = v;
        __syncthreads();
        for (int st = 128; st; st >>= 1) {
            if (threadIdx.x < st) red2[threadIdx.x] += red2[threadIdx.x + st];
            __syncthreads();
        }
        if (threadIdx.x == 0) {
            out[0] = red2[0] / (float)BATCH;
            g_cnt = 0;   // reset for next graph replay
        }
    }
}

// ---------------------------------------------------------------------------
extern "C" void kernel_launch(void* const* d_in, const int* in_sizes, int n_in,
                              void* d_out, int out_size) {
    const float* x       = (const float*)d_in[0];
    const float* w       = (const float*)d_in[1];
    const float* b       = (const float*)d_in[2];
    const int*   labels  = (const int*)d_in[3];
    const int*   sampled = (const int*)d_in[4];
    float* out = (float*)d_out;

    cudaFuncSetAttribute(gemm_lse_kernel,
                         cudaFuncAttributeMaxDynamicSharedMemorySize, SM_TOTAL);

    prep_kernel<<<PREP_GRID, 256>>>(x, w, b, sampled);
    gemm_lse_kernel<<<GEMM_BLKS + TRUE_BLKS, 256, SM_TOTAL>>>(x, w, b, labels);
    final_kernel<<<FIN_BLKS, 256>>>(out);
}

// round 15
// speedup vs baseline: 1.1568x; 1.0118x over previous
#include <cuda_runtime.h>
#include <cuda_bf16.h>
#include <math.h>
#include <stdint.h>

#define BATCH 4096
#define DIM 1024
#define NC 100000
#define NS 5000
#define NS_PAD 5120
#define LSE_OFF 20.0f

// Pure bf16 GEMM: K = DIM = 1024
#define KTOT 1024
#define TM 128
#define TN 128
#define TK 64
#define NKT (KTOT / TK)          // 16
#define NTN (NS_PAD / TN)        // 40 n-tiles
#define NTM (BATCH / TM)         // 32 m-tiles
#define GEMM_BLKS (NTN * NTM)    // 1280
#define TRUE_BLKS 512            // 8 rows per block
#define NSLOT (NTN * 4 + 1)      // one slot per (n-tile, n-warp) + true slot
#define NSTAGE 3

// Prep: value-bucketed gather (2560 buckets over class space) + convert
#define GATHER_BLKS 2560
#define CONV_BLKS 1024           // 4 rows per block; first 120 also zero pad rows
#define PREP_GRID (GATHER_BLKS + CONV_BLKS)
#define MAX_BUCKET 1024          // smem list capacity (expected ~2 per bucket)

#define FIN_BLKS 512             // warp-per-row final reduction

// ---------------------------------------------------------------------------
// Device scratch
// ---------------------------------------------------------------------------
__device__ __nv_bfloat16 g_a[(size_t)BATCH * KTOT];    // bf16(x)
__device__ __nv_bfloat16 g_b[(size_t)NS_PAD * KTOT];   // bf16(w[:, sampled])
__device__ float g_soff[NS_PAD];                       // expf(b - lec - LSE_OFF), 0 for pad
__device__ float g_true[BATCH];
__device__ float g_partial[BATCH * NSLOT];
__device__ float g_fin[FIN_BLKS];
__device__ int g_cnt;

// ---------------------------------------------------------------------------
// PTX helpers (family-portable only)
// ---------------------------------------------------------------------------
__device__ __forceinline__ uint32_t smem_u32(const void* p) {
    uint32_t a;
    asm("{ .reg .u64 t; cvta.to.shared.u64 t, %1; cvt.u32.u64 %0, t; }" : "=r"(a) : "l"(p));
    return a;
}
#define CP_ASYNC16(dst, src) \
    asm volatile("cp.async.cg.shared.global [%0], [%1], 16;" :: "r"(dst), "l"(src))
#define CP_COMMIT() asm volatile("cp.async.commit_group;" ::: "memory")
#define CP_WAIT(n)  asm volatile("cp.async.wait_group %0;" :: "n"(n) : "memory")

#define LDSM_X4(r0, r1, r2, r3, addr) \
    asm volatile("ldmatrix.sync.aligned.m8n8.x4.shared.b16 {%0,%1,%2,%3}, [%4];" \
        : "=r"(r0), "=r"(r1), "=r"(r2), "=r"(r3) : "r"(addr))

#define MMA16816(d, a, b) \
    asm volatile("mma.sync.aligned.m16n8k16.row.col.f32.bf16.bf16.f32 " \
        "{%0,%1,%2,%3}, {%4,%5,%6,%7}, {%8,%9}, {%0,%1,%2,%3};" \
        : "+f"((d)[0]), "+f"((d)[1]), "+f"((d)[2]), "+f"((d)[3]) \
        : "r"((a)[0]), "r"((a)[1]), "r"((a)[2]), "r"((a)[3]), "r"((b)[0]), "r"((b)[1]))

__device__ __forceinline__ float log_expected_count(int c) {
    float cf = (float)c;
    float p = logf((cf + 2.0f) / (cf + 1.0f)) / logf((float)NC + 1.0f);
    return logf(-expm1f((float)NS * log1pf(-p)));
}

// ---------------------------------------------------------------------------
// Kernel 1 (prep): value-bucketed gather of w[:, sampled] + convert x -> bf16
// Gather blocks [0, 2560): bucket b owns classes c with c*2560/100000 == b.
// Processing columns in class-value order gives DRAM row-buffer locality and
// L2 sector sharing for nearby sampled classes.
// ---------------------------------------------------------------------------
__global__ void prep_kernel(const float* __restrict__ x,
                            const float* __restrict__ w,
                            const float* __restrict__ b,
                            const int* __restrict__ sampled) {
    int blk = blockIdx.x;
    int tid = threadIdx.x;

    if (blk < GATHER_BLKS) {
        // --- scan sampled[] for classes in this bucket ---
        __shared__ int s_list[MAX_BUCKET];   // packed (c << 13) | s
        __shared__ int s_cnt;
        if (tid == 0) s_cnt = 0;
        __syncthreads();
        for (int s = tid; s < NS; s += 256) {
            int c = __ldg(sampled + s);
            int bk = (int)(((uint64_t)(uint32_t)c * GATHER_BLKS) / NC);
            if (bk == blk) {
                int p = atomicAdd(&s_cnt, 1);
                if (p < MAX_BUCKET) s_list[p] = (c << 13) | s;
            }
        }
        __syncthreads();
        int m = s_cnt < MAX_BUCKET ? s_cnt : MAX_BUCKET;

        // --- gather each owned column (value-ordered across blocks) ---
        for (int e = 0; e < m; e++) {
            int pk = s_list[e];
            int s = pk & 0x1FFF;
            int c = pk >> 13;
            const float* wc = w + c;
            __nv_bfloat16* br = g_b + (size_t)s * KTOT;
            float v[4];
            #pragma unroll
            for (int u = 0; u < 4; u++)
                v[u] = wc[(size_t)(tid + u * 256) * NC];
            #pragma unroll
            for (int u = 0; u < 4; u++)
                br[tid + u * 256] = __float2bfloat16(v[u]);
        }
        // --- per-sample exp factors for this bucket ---
        for (int e = tid; e < m; e += 256) {
            int pk = s_list[e];
            int s = pk & 0x1FFF;
            int c = pk >> 13;
            g_soff[s] = expf(b[c] - log_expected_count(c) - LSE_OFF);
        }
    } else {
        // --- convert x -> bf16, 4 rows per block ---
        int idx = blk - GATHER_BLKS;
        int r0 = idx * 4;
        #pragma unroll
        for (int rr = 0; rr < 4; rr++) {
            const float4 v = *(const float4*)(x + (size_t)(r0 + rr) * DIM + tid * 4);
            __nv_bfloat162* ar = (__nv_bfloat162*)(g_a + (size_t)(r0 + rr) * KTOT);
            ar[tid * 2]     = __floats2bfloat162_rn(v.x, v.y);
            ar[tid * 2 + 1] = __floats2bfloat162_rn(v.z, v.w);
        }
        // --- pad rows [NS, NS_PAD): zero g_b row + soff ---
        if (idx < NS_PAD - NS) {
            int s = NS + idx;
            int2* br = (int2*)(g_b + (size_t)s * KTOT);
            br[tid] = make_int2(0, 0);      // 256 x 8B = 2KB row
            if (tid == 0) g_soff[s] = 0.0f;
        }
    }
}

// ---------------------------------------------------------------------------
// Kernel 2: bf16 mma.sync GEMM 128x128xK1024 (blocks 0..1279) +
//           true-logit warp-dots (blocks 1280..1791), fused LSE epilogue
// SMEM per stage: A 16KB + B 16KB = 32KB; 3 stages = 96KB; soff 512B
// ---------------------------------------------------------------------------
#define STAGE_BYTES 32768
#define STAGE_A 0
#define STAGE_B 16384
#define SM_SOFF (NSTAGE * STAGE_BYTES)       // 98304
#define SM_TOTAL (SM_SOFF + TN * 4)          // 98816

__global__ __launch_bounds__(256, 2)
void gemm_lse_kernel(const float* __restrict__ x,
                     const float* __restrict__ w,
                     const float* __restrict__ b,
                     const int* __restrict__ labels) {
    int tid = threadIdx.x;

    // ---- true-logit blocks (fill GEMM tail waves) ----
    if (blockIdx.x >= GEMM_BLKS) {
        int r = (blockIdx.x - GEMM_BLKS) * 8 + (tid >> 5);
        int lane = tid & 31;
        int c = labels[r];
        const float* xr = x + (size_t)r * DIM;
        const float* wc = w + c;
        float s = 0.0f;
        #pragma unroll
        for (int u = 0; u < 8; u++) {
            float s2 = 0.0f;
            #pragma unroll
            for (int q = 0; q < 4; q++) {
                int d = lane + (u * 4 + q) * 32;
                s2 += xr[d] * wc[(size_t)d * NC];
            }
            s += s2;
        }
        #pragma unroll
        for (int o = 16; o; o >>= 1)
            s += __shfl_xor_sync(0xffffffffu, s, o);
        if (lane == 0) {
            float t = s + b[c] - log_expected_count(c);
            g_true[r] = t;
            g_partial[r * NSLOT + NSLOT - 1] = expf(t - LSE_OFF);
        }
        return;
    }

    // ---- GEMM blocks ----
    extern __shared__ char smem[];
    const uint32_t sbase = smem_u32(smem);
    float* soff_s = (float*)(smem + SM_SOFF);

    int lane = tid & 31;
    int wid = tid >> 5;
    int wm = wid & 1;          // 2 m-warps (64 rows each)
    int wn = wid >> 1;         // 4 n-warps (32 cols each)
    int bn = blockIdx.x % NTN;
    int bm = blockIdx.x / NTN;
    int m0 = bm * TM;
    int n0 = bn * TN;

    const __nv_bfloat16* ga = g_a + (size_t)m0 * KTOT;
    const __nv_bfloat16* gb = g_b + (size_t)n0 * KTOT;

    if (tid < TN) soff_s[tid] = g_soff[n0 + tid];

    int lrow = tid >> 3;            // 0..31 (+32 per i)
    int lc   = tid & 7;             // 16B chunk 0..7
    uint32_t swrow = (uint32_t)(lrow * 128 + ((lc ^ (lrow & 7)) * 16));

    float acc[4][4][4];
    #pragma unroll
    for (int i = 0; i < 4; i++)
        #pragma unroll
        for (int j = 0; j < 4; j++)
            #pragma unroll
            for (int v = 0; v < 4; v++) acc[i][j][v] = 0.0f;

    // Prologue: prefetch stages 0 and 1
    #pragma unroll
    for (int pf = 0; pf < 2; pf++) {
        uint32_t sb = sbase + pf * STAGE_BYTES;
        int kk = pf * TK;
        #pragma unroll
        for (int i = 0; i < 4; i++) {
            int row = lrow + i * 32;
            CP_ASYNC16(sb + STAGE_A + swrow + (uint32_t)(i * 32 * 128),
                       ga + (size_t)row * KTOT + kk + lc * 8);
            CP_ASYNC16(sb + STAGE_B + swrow + (uint32_t)(i * 32 * 128),
                       gb + (size_t)row * KTOT + kk + lc * 8);
        }
        CP_COMMIT();
    }

    // LDSM base offsets; across ks-steps the swizzled address is off ^ (ks*32)
    int mat = lane >> 3;
    int lr8 = lane & 7;
    int msel = (mat & 1) << 3;
    int csel = mat >> 1;

    uint32_t offA[4], offB[2];
    #pragma unroll
    for (int i = 0; i < 4; i++) {
        int r = wm * 64 + i * 16 + lr8 + msel;
        offA[i] = (uint32_t)(r * 128 + ((csel ^ (r & 7)) * 16));
    }
    #pragma unroll
    for (int p = 0; p < 2; p++) {
        int r = wn * 32 + p * 16 + lr8 + msel;
        offB[p] = (uint32_t)(r * 128 + ((csel ^ (r & 7)) * 16));
    }

    int sidx = 0;
    for (int it = 0; it < NKT; it++) {
        if (it < NKT - 1) { CP_WAIT(1); } else { CP_WAIT(0); }
        __syncthreads();

        if (it + 2 < NKT) {
            int pidx = sidx + 2; if (pidx >= NSTAGE) pidx -= NSTAGE;
            uint32_t sb = sbase + pidx * STAGE_BYTES;
            int kk = (it + 2) * TK;
            #pragma unroll
            for (int i = 0; i < 4; i++) {
                int row = lrow + i * 32;
                CP_ASYNC16(sb + STAGE_A + swrow + (uint32_t)(i * 32 * 128),
                           ga + (size_t)row * KTOT + kk + lc * 8);
                CP_ASYNC16(sb + STAGE_B + swrow + (uint32_t)(i * 32 * 128),
                           gb + (size_t)row * KTOT + kk + lc * 8);
            }
            CP_COMMIT();
        }

        uint32_t abase = sbase + sidx * STAGE_BYTES + STAGE_A;
        uint32_t bbase = sbase + sidx * STAGE_BYTES + STAGE_B;

        #pragma unroll
        for (int ks = 0; ks < 4; ks++) {
            uint32_t kx = (uint32_t)(ks * 32);
            uint32_t a[4][4], bfr[4][2];
            #pragma unroll
            for (int i = 0; i < 4; i++)
                LDSM_X4(a[i][0], a[i][1], a[i][2], a[i][3], abase + (offA[i] ^ kx));
            #pragma unroll
            for (int p = 0; p < 2; p++) {
                uint32_t t0, t1, t2, t3;
                LDSM_X4(t0, t1, t2, t3, bbase + (offB[p] ^ kx));
                bfr[2 * p][0] = t0;     bfr[2 * p][1] = t2;
                bfr[2 * p + 1][0] = t1; bfr[2 * p + 1][1] = t3;
            }
            #pragma unroll
            for (int i = 0; i < 4; i++)
                #pragma unroll
                for (int j = 0; j < 4; j++)
                    MMA16816(acc[i][j], a[i], bfr[j]);
        }
        sidx++; if (sidx >= NSTAGE) sidx = 0;
    }

    // Fused epilogue: sum += __expf(acc) * exp_factor (pad cols have factor 0)
    float sr0[4], sr1[4];
    #pragma unroll
    for (int i = 0; i < 4; i++) { sr0[i] = 0.0f; sr1[i] = 0.0f; }

    #pragma unroll
    for (int j = 0; j < 4; j++) {
        int l = wn * 32 + j * 8 + 2 * (lane & 3);
        float e0 = soff_s[l];
        float e1 = soff_s[l + 1];
        #pragma unroll
        for (int i = 0; i < 4; i++) {
            sr0[i] = fmaf(__expf(acc[i][j][0]), e0, sr0[i]);
            sr0[i] = fmaf(__expf(acc[i][j][1]), e1, sr0[i]);
            sr1[i] = fmaf(__expf(acc[i][j][2]), e0, sr1[i]);
            sr1[i] = fmaf(__expf(acc[i][j][3]), e1, sr1[i]);
        }
    }
    #pragma unroll
    for (int i = 0; i < 4; i++) {
        sr0[i] += __shfl_xor_sync(0xffffffffu, sr0[i], 1);
        sr0[i] += __shfl_xor_sync(0xffffffffu, sr0[i], 2);
        sr1[i] += __shfl_xor_sync(0xffffffffu, sr1[i], 1);
        sr1[i] += __shfl_xor_sync(0xffffffffu, sr1[i], 2);
    }
    if ((lane & 3) == 0) {
        int slot = bn * 4 + wn;
        #pragma unroll
        for (int i = 0; i < 4; i++) {
            int r0 = m0 + wm * 64 + i * 16 + (lane >> 2);
            g_partial[r0 * NSLOT + slot] = sr0[i];
            g_partial[(r0 + 8) * NSLOT + slot] = sr1[i];
        }
    }
}

// ---------------------------------------------------------------------------
// Kernel 3: final reduction, warp-per-row (512 blocks x 256 thr); last block
//           sums the 512 block partials. Counter self-resets for graph replay.
// ---------------------------------------------------------------------------
__global__ void final_kernel(float* __restrict__ out) {
    __shared__ float red[8];
    __shared__ int is_last;
    int wid = threadIdx.x >> 5;
    int lane = threadIdx.x & 31;
    int r = blockIdx.x * 8 + wid;

    const float* row = g_partial + (size_t)r * NSLOT;
    float s = 0.0f;
    #pragma unroll
    for (int t = lane; t < NSLOT; t += 32)
        s += row[t];
    #pragma unroll
    for (int o = 16; o; o >>= 1)
        s += __shfl_xor_sync(0xffffffffu, s, o);
    if (lane == 0)
        red[wid] = LSE_OFF + logf(s) - g_true[r];
    __syncthreads();

    if (threadIdx.x == 0) {
        float acc = 0.0f;
        #pragma unroll
        for (int i = 0; i < 8; i++) acc += red[i];
        g_fin[blockIdx.x] = acc;
        __threadfence();
        int old = atomicAdd(&g_cnt, 1);
        is_last = (old == FIN_BLKS - 1) ? 1 : 0;
    }
    __syncthreads();

    if (is_last) {
        __threadfence();
        float v = g_fin[threadIdx.x] + g_fin[threadIdx.x + 256];
        __shared__ float red2[256];
        red2[threadIdx.x] = v;
        __syncthreads();
        for (int st = 128; st; st >>= 1) {
            if (threadIdx.x < st) red2[threadIdx.x] += red2[threadIdx.x + st];
            __syncthreads();
        }
        if (threadIdx.x == 0) {
            out[0] = red2[0] / (float)BATCH;
            g_cnt = 0;   // reset for next graph replay
        }
    }
}

// ---------------------------------------------------------------------------
extern "C" void kernel_launch(void* const* d_in, const int* in_sizes, int n_in,
                              void* d_out, int out_size) {
    const float* x       = (const float*)d_in[0];
    const float* w       = (const float*)d_in[1];
    const float* b       = (const float*)d_in[2];
    const int*   labels  = (const int*)d_in[3];
    const int*   sampled = (const int*)d_in[4];
    float* out = (float*)d_out;

    cudaFuncSetAttribute(gemm_lse_kernel,
                         cudaFuncAttributeMaxDynamicSharedMemorySize, SM_TOTAL);

    prep_kernel<<<PREP_GRID, 256>>>(x, w, b, sampled);
    gemm_lse_kernel<<<GEMM_BLKS + TRUE_BLKS, 256, SM_TOTAL>>>(x, w, b, labels);
    final_kernel<<<FIN_BLKS, 256>>>(out);
}

// round 16
// speedup vs baseline: 1.1841x; 1.0236x over previous
#include <cuda_runtime.h>
#include <cuda_bf16.h>
#include <math.h>
#include <stdint.h>

#define BATCH 4096
#define DIM 1024
#define NC 100000
#define NS 5000
#define NS_PAD 5120
#define LSE_OFF 20.0f

// Pure bf16 GEMM: K = DIM = 1024
#define KTOT 1024
#define TM 128
#define TN 128
#define TK 64
#define NKT (KTOT / TK)          // 16
#define NTN (NS_PAD / TN)        // 40 n-tiles
#define NTM (BATCH / TM)         // 32 m-tiles
#define GEMM_BLKS (NTN * NTM)    // 1280
#define TRUE_BLKS 512            // 8 rows per block
#define NSLOT (NTN * 4 + 1)      // one slot per (n-tile, n-warp) + true slot
#define NSTAGE 3

// Prep: 640 value-buckets (~8 cols each, 156-class window = 1 DRAM row) + convert
#define GATHER_BLKS 640
#define CONV_BLKS 1024           // 4 rows per block; first 120 also zero pad rows
#define PREP_GRID (GATHER_BLKS + CONV_BLKS)
#define MAX_BUCKET 96            // mean 7.8, Poisson tail far below 96

#define FIN_BLKS 512             // warp-per-row final reduction

// ---------------------------------------------------------------------------
// Device scratch
// ---------------------------------------------------------------------------
__device__ __nv_bfloat16 g_a[(size_t)BATCH * KTOT];    // bf16(x)
__device__ __nv_bfloat16 g_b[(size_t)NS_PAD * KTOT];   // bf16(w[:, sampled])
__device__ float g_soff[NS_PAD];                       // expf(b - lec - LSE_OFF), 0 for pad
__device__ float g_true[BATCH];
__device__ float g_partial[BATCH * NSLOT];
__device__ float g_fin[FIN_BLKS];
__device__ int g_cnt;

// ---------------------------------------------------------------------------
// PTX helpers (family-portable only)
// ---------------------------------------------------------------------------
__device__ __forceinline__ uint32_t smem_u32(const void* p) {
    uint32_t a;
    asm("{ .reg .u64 t; cvta.to.shared.u64 t, %1; cvt.u32.u64 %0, t; }" : "=r"(a) : "l"(p));
    return a;
}
#define CP_ASYNC16(dst, src) \
    asm volatile("cp.async.cg.shared.global [%0], [%1], 16;" :: "r"(dst), "l"(src))
#define CP_COMMIT() asm volatile("cp.async.commit_group;" ::: "memory")
#define CP_WAIT(n)  asm volatile("cp.async.wait_group %0;" :: "n"(n) : "memory")

#define LDSM_X4(r0, r1, r2, r3, addr) \
    asm volatile("ldmatrix.sync.aligned.m8n8.x4.shared.b16 {%0,%1,%2,%3}, [%4];" \
        : "=r"(r0), "=r"(r1), "=r"(r2), "=r"(r3) : "r"(addr))

#define MMA16816(d, a, b) \
    asm volatile("mma.sync.aligned.m16n8k16.row.col.f32.bf16.bf16.f32 " \
        "{%0,%1,%2,%3}, {%4,%5,%6,%7}, {%8,%9}, {%0,%1,%2,%3};" \
        : "+f"((d)[0]), "+f"((d)[1]), "+f"((d)[2]), "+f"((d)[3]) \
        : "r"((a)[0]), "r"((a)[1]), "r"((a)[2]), "r"((a)[3]), "r"((b)[0]), "r"((b)[1]))

__device__ __forceinline__ float log_expected_count(int c) {
    float cf = (float)c;
    float p = logf((cf + 2.0f) / (cf + 1.0f)) / logf((float)NC + 1.0f);
    return logf(-expm1f((float)NS * log1pf(-p)));
}

// ---------------------------------------------------------------------------
// Kernel 1 (prep): row-locality gather of w[:, sampled] + convert x -> bf16
// Gather block b owns sampled classes in window [b*156.25, (b+1)*156.25).
// For each d (one per thread per u-step), the block's columns are swept in
// the INNER loop: their addresses lie within 624B -> same DRAM row (row-buffer
// hits) and shared 32B sectors for close classes.
// ---------------------------------------------------------------------------
__global__ void prep_kernel(const float* __restrict__ x,
                            const float* __restrict__ w,
                            const float* __restrict__ b,
                            const int* __restrict__ sampled) {
    int blk = blockIdx.x;
    int tid = threadIdx.x;

    if (blk < GATHER_BLKS) {
        // --- scan sampled[] for classes in this bucket ---
        __shared__ int s_list[MAX_BUCKET];   // packed (c << 13) | s
        __shared__ int s_cnt;
        if (tid == 0) s_cnt = 0;
        __syncthreads();
        for (int s = tid; s < NS; s += 256) {
            int c = __ldg(sampled + s);
            int bk = (int)(((uint64_t)(uint32_t)c * GATHER_BLKS) / NC);
            if (bk == blk) {
                int p = atomicAdd(&s_cnt, 1);
                if (p < MAX_BUCKET) s_list[p] = (c << 13) | s;
            }
        }
        __syncthreads();
        int m = s_cnt < MAX_BUCKET ? s_cnt : MAX_BUCKET;

        // --- gather: d per thread (4 steps), columns inner in chunks of 4 ---
        #pragma unroll
        for (int u = 0; u < 4; u++) {
            int d = tid + u * 256;
            const float* wd = w + (size_t)d * NC;
            for (int e0 = 0; e0 < m; e0 += 4) {
                float v[4];
                int cc[4], ss[4];
                int lim = m - e0 < 4 ? m - e0 : 4;
                #pragma unroll
                for (int q = 0; q < 4; q++) {
                    if (q < lim) {
                        int pk = s_list[e0 + q];
                        cc[q] = pk >> 13;
                        ss[q] = pk & 0x1FFF;
                        v[q] = wd[cc[q]];
                    }
                }
                #pragma unroll
                for (int q = 0; q < 4; q++) {
                    if (q < lim)
                        g_b[(size_t)ss[q] * KTOT + d] = __float2bfloat16(v[q]);
                }
            }
        }
        // --- per-sample exp factors for this bucket ---
        for (int e = tid; e < m; e += 256) {
            int pk = s_list[e];
            int s = pk & 0x1FFF;
            int c = pk >> 13;
            g_soff[s] = expf(b[c] - log_expected_count(c) - LSE_OFF);
        }
    } else {
        // --- convert x -> bf16, 4 rows per block ---
        int idx = blk - GATHER_BLKS;
        int r0 = idx * 4;
        #pragma unroll
        for (int rr = 0; rr < 4; rr++) {
            const float4 v = *(const float4*)(x + (size_t)(r0 + rr) * DIM + tid * 4);
            __nv_bfloat162* ar = (__nv_bfloat162*)(g_a + (size_t)(r0 + rr) * KTOT);
            ar[tid * 2]     = __floats2bfloat162_rn(v.x, v.y);
            ar[tid * 2 + 1] = __floats2bfloat162_rn(v.z, v.w);
        }
        // --- pad rows [NS, NS_PAD): zero g_b row + soff ---
        if (idx < NS_PAD - NS) {
            int s = NS + idx;
            int2* br = (int2*)(g_b + (size_t)s * KTOT);
            br[tid] = make_int2(0, 0);      // 256 x 8B = 2KB row
            if (tid == 0) g_soff[s] = 0.0f;
        }
    }
}

// ---------------------------------------------------------------------------
// Kernel 2: bf16 mma.sync GEMM 128x128xK1024 (blocks 0..1279) +
//           true-logit warp-dots (blocks 1280..1791), fused LSE epilogue
// SMEM per stage: A 16KB + B 16KB = 32KB; 3 stages = 96KB; soff 512B
// ---------------------------------------------------------------------------
#define STAGE_BYTES 32768
#define STAGE_A 0
#define STAGE_B 16384
#define SM_SOFF (NSTAGE * STAGE_BYTES)       // 98304
#define SM_TOTAL (SM_SOFF + TN * 4)          // 98816

__global__ __launch_bounds__(256, 2)
void gemm_lse_kernel(const float* __restrict__ x,
                     const float* __restrict__ w,
                     const float* __restrict__ b,
                     const int* __restrict__ labels) {
    int tid = threadIdx.x;

    // ---- true-logit blocks (fill GEMM tail waves) ----
    if (blockIdx.x >= GEMM_BLKS) {
        int r = (blockIdx.x - GEMM_BLKS) * 8 + (tid >> 5);
        int lane = tid & 31;
        int c = labels[r];
        const float* xr = x + (size_t)r * DIM;
        const float* wc = w + c;
        float s = 0.0f;
        #pragma unroll
        for (int u = 0; u < 8; u++) {
            float s2 = 0.0f;
            #pragma unroll
            for (int q = 0; q < 4; q++) {
                int d = lane + (u * 4 + q) * 32;
                s2 += xr[d] * wc[(size_t)d * NC];
            }
            s += s2;
        }
        #pragma unroll
        for (int o = 16; o; o >>= 1)
            s += __shfl_xor_sync(0xffffffffu, s, o);
        if (lane == 0) {
            float t = s + b[c] - log_expected_count(c);
            g_true[r] = t;
            g_partial[r * NSLOT + NSLOT - 1] = expf(t - LSE_OFF);
        }
        return;
    }

    // ---- GEMM blocks ----
    extern __shared__ char smem[];
    const uint32_t sbase = smem_u32(smem);
    float* soff_s = (float*)(smem + SM_SOFF);

    int lane = tid & 31;
    int wid = tid >> 5;
    int wm = wid & 1;          // 2 m-warps (64 rows each)
    int wn = wid >> 1;         // 4 n-warps (32 cols each)
    int bn = blockIdx.x % NTN;
    int bm = blockIdx.x / NTN;
    int m0 = bm * TM;
    int n0 = bn * TN;

    const __nv_bfloat16* ga = g_a + (size_t)m0 * KTOT;
    const __nv_bfloat16* gb = g_b + (size_t)n0 * KTOT;

    if (tid < TN) soff_s[tid] = g_soff[n0 + tid];

    int lrow = tid >> 3;            // 0..31 (+32 per i)
    int lc   = tid & 7;             // 16B chunk 0..7
    uint32_t swrow = (uint32_t)(lrow * 128 + ((lc ^ (lrow & 7)) * 16));

    float acc[4][4][4];
    #pragma unroll
    for (int i = 0; i < 4; i++)
        #pragma unroll
        for (int j = 0; j < 4; j++)
            #pragma unroll
            for (int v = 0; v < 4; v++) acc[i][j][v] = 0.0f;

    // Prologue: prefetch stages 0 and 1
    #pragma unroll
    for (int pf = 0; pf < 2; pf++) {
        uint32_t sb = sbase + pf * STAGE_BYTES;
        int kk = pf * TK;
        #pragma unroll
        for (int i = 0; i < 4; i++) {
            int row = lrow + i * 32;
            CP_ASYNC16(sb + STAGE_A + swrow + (uint32_t)(i * 32 * 128),
                       ga + (size_t)row * KTOT + kk + lc * 8);
            CP_ASYNC16(sb + STAGE_B + swrow + (uint32_t)(i * 32 * 128),
                       gb + (size_t)row * KTOT + kk + lc * 8);
        }
        CP_COMMIT();
    }

    // LDSM base offsets; across ks-steps the swizzled address is off ^ (ks*32)
    int mat = lane >> 3;
    int lr8 = lane & 7;
    int msel = (mat & 1) << 3;
    int csel = mat >> 1;

    uint32_t offA[4], offB[2];
    #pragma unroll
    for (int i = 0; i < 4; i++) {
        int r = wm * 64 + i * 16 + lr8 + msel;
        offA[i] = (uint32_t)(r * 128 + ((csel ^ (r & 7)) * 16));
    }
    #pragma unroll
    for (int p = 0; p < 2; p++) {
        int r = wn * 32 + p * 16 + lr8 + msel;
        offB[p] = (uint32_t)(r * 128 + ((csel ^ (r & 7)) * 16));
    }

    int sidx = 0;
    for (int it = 0; it < NKT; it++) {
        if (it < NKT - 1) { CP_WAIT(1); } else { CP_WAIT(0); }
        __syncthreads();

        if (it + 2 < NKT) {
            int pidx = sidx + 2; if (pidx >= NSTAGE) pidx -= NSTAGE;
            uint32_t sb = sbase + pidx * STAGE_BYTES;
            int kk = (it + 2) * TK;
            #pragma unroll
            for (int i = 0; i < 4; i++) {
                int row = lrow + i * 32;
                CP_ASYNC16(sb + STAGE_A + swrow + (uint32_t)(i * 32 * 128),
                           ga + (size_t)row * KTOT + kk + lc * 8);
                CP_ASYNC16(sb + STAGE_B + swrow + (uint32_t)(i * 32 * 128),
                           gb + (size_t)row * KTOT + kk + lc * 8);
            }
            CP_COMMIT();
        }

        uint32_t abase = sbase + sidx * STAGE_BYTES + STAGE_A;
        uint32_t bbase = sbase + sidx * STAGE_BYTES + STAGE_B;

        #pragma unroll
        for (int ks = 0; ks < 4; ks++) {
            uint32_t kx = (uint32_t)(ks * 32);
            uint32_t a[4][4], bfr[4][2];
            #pragma unroll
            for (int i = 0; i < 4; i++)
                LDSM_X4(a[i][0], a[i][1], a[i][2], a[i][3], abase + (offA[i] ^ kx));
            #pragma unroll
            for (int p = 0; p < 2; p++) {
                uint32_t t0, t1, t2, t3;
                LDSM_X4(t0, t1, t2, t3, bbase + (offB[p] ^ kx));
                bfr[2 * p][0] = t0;     bfr[2 * p][1] = t2;
                bfr[2 * p + 1][0] = t1; bfr[2 * p + 1][1] = t3;
            }
            #pragma unroll
            for (int i = 0; i < 4; i++)
                #pragma unroll
                for (int j = 0; j < 4; j++)
                    MMA16816(acc[i][j], a[i], bfr[j]);
        }
        sidx++; if (sidx >= NSTAGE) sidx = 0;
    }

    // Fused epilogue: sum += __expf(acc) * exp_factor (pad cols have factor 0)
    float sr0[4], sr1[4];
    #pragma unroll
    for (int i = 0; i < 4; i++) { sr0[i] = 0.0f; sr1[i] = 0.0f; }

    #pragma unroll
    for (int j = 0; j < 4; j++) {
        int l = wn * 32 + j * 8 + 2 * (lane & 3);
        float e0 = soff_s[l];
        float e1 = soff_s[l + 1];
        #pragma unroll
        for (int i = 0; i < 4; i++) {
            sr0[i] = fmaf(__expf(acc[i][j][0]), e0, sr0[i]);
            sr0[i] = fmaf(__expf(acc[i][j][1]), e1, sr0[i]);
            sr1[i] = fmaf(__expf(acc[i][j][2]), e0, sr1[i]);
            sr1[i] = fmaf(__expf(acc[i][j][3]), e1, sr1[i]);
        }
    }
    #pragma unroll
    for (int i = 0; i < 4; i++) {
        sr0[i] += __shfl_xor_sync(0xffffffffu, sr0[i], 1);
        sr0[i] += __shfl_xor_sync(0xffffffffu, sr0[i], 2);
        sr1[i] += __shfl_xor_sync(0xffffffffu, sr1[i], 1);
        sr1[i] += __shfl_xor_sync(0xffffffffu, sr1[i], 2);
    }
    if ((lane & 3) == 0) {
        int slot = bn * 4 + wn;
        #pragma unroll
        for (int i = 0; i < 4; i++) {
            int r0 = m0 + wm * 64 + i * 16 + (lane >> 2);
            g_partial[r0 * NSLOT + slot] = sr0[i];
            g_partial[(r0 + 8) * NSLOT + slot] = sr1[i];
        }
    }
}

// ---------------------------------------------------------------------------
// Kernel 3: final reduction, warp-per-row (512 blocks x 256 thr); last block
//           sums the 512 block partials. Counter self-resets for graph replay.
// ---------------------------------------------------------------------------
__global__ void final_kernel(float* __restrict__ out) {
    __shared__ float red[8];
    __shared__ int is_last;
    int wid = threadIdx.x >> 5;
    int lane = threadIdx.x & 31;
    int r = blockIdx.x * 8 + wid;

    const float* row = g_partial + (size_t)r * NSLOT;
    float s = 0.0f;
    #pragma unroll
    for (int t = lane; t < NSLOT; t += 32)
        s += row[t];
    #pragma unroll
    for (int o = 16; o; o >>= 1)
        s += __shfl_xor_sync(0xffffffffu, s, o);
    if (lane == 0)
        red[wid] = LSE_OFF + logf(s) - g_true[r];
    __syncthreads();

    if (threadIdx.x == 0) {
        float acc = 0.0f;
        #pragma unroll
        for (int i = 0; i < 8; i++) acc += red[i];
        g_fin[blockIdx.x] = acc;
        __threadfence();
        int old = atomicAdd(&g_cnt, 1);
        is_last = (old == FIN_BLKS - 1) ? 1 : 0;
    }
    __syncthreads();

    if (is_last) {
        __threadfence();
        float v = g_fin[threadIdx.x] + g_fin[threadIdx.x + 256];
        __shared__ float red2[256];
        red2[threadIdx.x] = v;
        __syncthreads();
        for (int st = 128; st; st >>= 1) {
            if (threadIdx.x < st) red2[threadIdx.x] += red2[threadIdx.x + st];
            __syncthreads();
        }
        if (threadIdx.x == 0) {
            out[0] = red2[0] / (float)BATCH;
            g_cnt = 0;   // reset for next graph replay
        }
    }
}

// ---------------------------------------------------------------------------
extern "C" void kernel_launch(void* const* d_in, const int* in_sizes, int n_in,
                              void* d_out, int out_size) {
    const float* x       = (const float*)d_in[0];
    const float* w       = (const float*)d_in[1];
    const float* b       = (const float*)d_in[2];
    const int*   labels  = (const int*)d_in[3];
    const int*   sampled = (const int*)d_in[4];
    float* out = (float*)d_out;

    cudaFuncSetAttribute(gemm_lse_kernel,
                         cudaFuncAttributeMaxDynamicSharedMemorySize, SM_TOTAL);

    prep_kernel<<<PREP_GRID, 256>>>(x, w, b, sampled);
    gemm_lse_kernel<<<GEMM_BLKS + TRUE_BLKS, 256, SM_TOTAL>>>(x, w, b, labels);
    final_kernel<<<FIN_BLKS, 256>>>(out);
}